// round 9
// baseline (speedup 1.0000x reference)
#include <cuda_runtime.h>
#include <cuda_bf16.h>

// DET_PROB hierarchical cumprod expansion — v7: persistent + prefetch pipeline.
// B0=8, B1=16, B2=16 -> 2048 leaves/row, 128 leaf-groups of 16.
//
// Warp-tile = 32 contiguous leaf groups = 128 float4 chunks (1/4 row).
// Persistent grid (740 blocks, all resident). Each warp grid-strides over
// tiles; loads for tile t+1 are issued before tile t is processed, so every
// warp keeps 2KB of reads in flight continuously. No smem, no barriers,
// no wave transitions.

#define B0 8
#define B1 16
#define B2 16
#define ROW_ELEMS 2048
#define BLOCK 256
#define NBLOCKS 740                // 148 SMs x 5 resident blocks

__device__ __forceinline__ float tile_prefix(
    const float* __restrict__ dc0,
    const float* __restrict__ dc1,
    size_t T, int lane)
{
    size_t row = T >> 2;                       // 4 tiles per row
    int g  = (int)((T & 3) << 5) + lane;       // this lane's leaf group 0..127
    int a0 = g >> 4;
    int a1 = g & 15;

    // c0 = cumprod(dc0[row])[a0] — warp-broadcast L1 hits
    const float4* r0 = (const float4*)(dc0 + row * B0);
    float4 p0 = __ldg(&r0[0]);
    float4 p1 = __ldg(&r0[1]);
    float v0[8] = {p0.x, p0.y, p0.z, p0.w, p1.x, p1.y, p1.z, p1.w};
    float c0 = v0[0];
#pragma unroll
    for (int k = 1; k < B0; k++)
        c0 *= (k <= a0) ? v0[k] : 1.0f;

    // c1 = within-group cumprod of dc1[row, a0*16 .. +16][a1]
    const float4* r1 = (const float4*)(dc1 + row * (B0 * B1) + a0 * B1);
    float4 q0 = __ldg(&r1[0]);
    float4 q1 = __ldg(&r1[1]);
    float4 q2 = __ldg(&r1[2]);
    float4 q3 = __ldg(&r1[3]);
    float v1[16] = {q0.x, q0.y, q0.z, q0.w, q1.x, q1.y, q1.z, q1.w,
                    q2.x, q2.y, q2.z, q2.w, q3.x, q3.y, q3.z, q3.w};
    float c1 = v1[0];
#pragma unroll
    for (int k = 1; k < B1; k++)
        c1 *= (k <= a1) ? v1[k] : 1.0f;

    return c0 * c1;
}

__global__ __launch_bounds__(BLOCK, 5) void det_prob_kernel(
    const float* __restrict__ dc0,
    const float* __restrict__ dc1,
    const float* __restrict__ dc2,
    float* __restrict__ out,
    int ntiles, int nwarps)
{
    int lane = threadIdx.x & 31;
    size_t gwid = (size_t)blockIdx.x * (BLOCK / 32) + (threadIdx.x >> 5);
    if (gwid >= (size_t)ntiles) return;

    const float4* src = (const float4*)dc2;
    float4*       dst = (float4*)out;
    const unsigned mask = 0xFFFFFFFFu;
    int c    = lane & 3;               // chunk-within-group
    int gsel = lane >> 2;              // group slot within an iter

    // ---- prologue: load first tile ----
    size_t t = gwid;
    size_t base = t * 128 + lane;
    float4 x0 = __ldcs(&src[base]);
    float4 x1 = __ldcs(&src[base + 32]);
    float4 x2 = __ldcs(&src[base + 64]);
    float4 x3 = __ldcs(&src[base + 96]);

    while (true) {
        // ---- prefetch next tile's streaming loads (warp-uniform branch) ----
        size_t tn = t + (size_t)nwarps;
        bool more = tn < (size_t)ntiles;
        float4 y0, y1, y2, y3;
        if (more) {
            size_t nb = tn * 128 + lane;
            y0 = __ldcs(&src[nb]);
            y1 = __ldcs(&src[nb + 32]);
            y2 = __ldcs(&src[nb + 64]);
            y3 = __ldcs(&src[nb + 96]);
        }

        // ---- prefix for current tile (stalls covered by y-loads in flight) ----
        float pfx = tile_prefix(dc0, dc1, t, lane);

        // ---- process + store current tile ----
        float4 xs[4] = {x0, x1, x2, x3};
        size_t ob = t * 128 + lane;
#pragma unroll
        for (int it = 0; it < 4; it++) {
            float4 x = xs[it];
            float l0 = x.x;
            float l1 = l0 * x.y;
            float l2 = l1 * x.z;
            float l3 = l2 * x.w;

            // 4-lane segmented inclusive scan of chunk totals
            float s = l3;
            float u = __shfl_up_sync(mask, s, 1);
            if (c >= 1) s *= u;
            u = __shfl_up_sync(mask, s, 2);
            if (c >= 2) s *= u;
            float e = __shfl_up_sync(mask, s, 1);   // exclusive prefix
            if (c == 0) e = 1.0f;

            float pf = __shfl_sync(mask, pfx, it * 8 + gsel);
            float scale = pf * e;
            float4 o;
            o.x = l0 * scale;
            o.y = l1 * scale;
            o.z = l2 * scale;
            o.w = l3 * scale;
            __stcs(&dst[ob + it * 32], o);
        }

        if (!more) break;
        t = tn;
        x0 = y0; x1 = y1; x2 = y2; x3 = y3;
    }
}

extern "C" void kernel_launch(void* const* d_in, const int* in_sizes, int n_in,
                              void* d_out, int out_size) {
    const float* dc0 = (const float*)d_in[0];
    const float* dc1 = (const float*)d_in[1];
    const float* dc2 = (const float*)d_in[2];
    float* out = (float*)d_out;

    int ntiles = out_size / 512;                 // 128 float4 chunks per tile
    int nwarps = NBLOCKS * (BLOCK / 32);         // 5920 persistent warps
    det_prob_kernel<<<NBLOCKS, BLOCK>>>(dc0, dc1, dc2, out, ntiles, nwarps);
}

// round 10
// speedup vs baseline: 1.2516x; 1.2516x over previous
#include <cuda_runtime.h>
#include <cuda_bf16.h>

// DET_PROB hierarchical cumprod expansion — v8: v6 warp-autonomous structure,
// BLOCK=512 scheduling granularity, explicit regs (no array round-trip).
// B0=8, B1=16, B2=16 -> 2048 leaves/row, 128 leaf-groups of 16.
//
// One warp owns 32 contiguous leaf groups (128 chunks = 1/4 row).
//  - 4 front-batched streaming float4 loads per lane (MLP=4, .cs).
//  - One prefix per lane (registers only), latency hidden under loads.
//  - No smem, no __syncthreads. Segmented 4-lane shfl scan per chunk.

#define B0 8
#define B1 16
#define B2 16
#define ROW_ELEMS 2048
#define BLOCK 512                  // 16 warps

__global__ __launch_bounds__(BLOCK) void det_prob_kernel(
    const float* __restrict__ dc0,
    const float* __restrict__ dc1,
    const float* __restrict__ dc2,
    float* __restrict__ out)
{
    int tid  = threadIdx.x;
    int lane = tid & 31;
    size_t gwid = (size_t)blockIdx.x * (BLOCK / 32) + (tid >> 5);

    size_t chunk_base = gwid * 128 + lane;      // float4 units
    const float4* src = (const float4*)dc2;
    float4*       dst = (float4*)out;

    // ---------- Phase 0: front-batch 4 streaming loads ----------
    float4 x0 = __ldcs(&src[chunk_base + 0 * 32]);
    float4 x1 = __ldcs(&src[chunk_base + 1 * 32]);
    float4 x2 = __ldcs(&src[chunk_base + 2 * 32]);
    float4 x3 = __ldcs(&src[chunk_base + 3 * 32]);

    // ---------- Phase 1: one prefix per lane (overlaps loads) ----------
    size_t gbase = gwid * 32;                   // first leaf group of warp
    size_t row   = gbase >> 7;
    int g  = (int)((gbase + lane) & 127);
    int a0 = g >> 4;
    int a1 = g & 15;

    float pfx;
    {
        // c0 = cumprod(dc0[row])[a0] — warp-broadcast L1 hits
        const float4* r0 = (const float4*)(dc0 + row * B0);
        float4 p0 = __ldg(&r0[0]);
        float4 p1 = __ldg(&r0[1]);
        float v0[8] = {p0.x, p0.y, p0.z, p0.w, p1.x, p1.y, p1.z, p1.w};
        float c0 = v0[0];
#pragma unroll
        for (int k = 1; k < B0; k++)
            c0 *= (k <= a0) ? v0[k] : 1.0f;

        // c1 = within-group cumprod of dc1[row, a0*16 .. +16][a1]
        const float4* r1 = (const float4*)(dc1 + row * (B0 * B1) + a0 * B1);
        float4 q0 = __ldg(&r1[0]);
        float4 q1 = __ldg(&r1[1]);
        float4 q2 = __ldg(&r1[2]);
        float4 q3 = __ldg(&r1[3]);
        float v1[16] = {q0.x, q0.y, q0.z, q0.w, q1.x, q1.y, q1.z, q1.w,
                        q2.x, q2.y, q2.z, q2.w, q3.x, q3.y, q3.z, q3.w};
        float c1 = v1[0];
#pragma unroll
        for (int k = 1; k < B1; k++)
            c1 *= (k <= a1) ? v1[k] : 1.0f;

        pfx = c0 * c1;
    }

    // ---------- Phase 2: scan + scale + store (no barrier) ----------
    const unsigned mask = 0xFFFFFFFFu;
    int c    = lane & 3;              // chunk-within-group
    int gsel = lane >> 2;             // group slot within an iter

#define PROCESS(X, IT)                                                    \
    {                                                                     \
        float l0 = (X).x;                                                 \
        float l1 = l0 * (X).y;                                            \
        float l2 = l1 * (X).z;                                            \
        float l3 = l2 * (X).w;                                            \
        float s = l3;                                                     \
        float u = __shfl_up_sync(mask, s, 1);                             \
        if (c >= 1) s *= u;                                               \
        u = __shfl_up_sync(mask, s, 2);                                   \
        if (c >= 2) s *= u;                                               \
        float e = __shfl_up_sync(mask, s, 1);                             \
        if (c == 0) e = 1.0f;                                             \
        float pf = __shfl_sync(mask, pfx, (IT) * 8 + gsel);               \
        float scale = pf * e;                                             \
        float4 o;                                                         \
        o.x = l0 * scale;                                                 \
        o.y = l1 * scale;                                                 \
        o.z = l2 * scale;                                                 \
        o.w = l3 * scale;                                                 \
        __stcs(&dst[chunk_base + (IT) * 32], o);                          \
    }

    PROCESS(x0, 0)
    PROCESS(x1, 1)
    PROCESS(x2, 2)
    PROCESS(x3, 3)
#undef PROCESS
}

extern "C" void kernel_launch(void* const* d_in, const int* in_sizes, int n_in,
                              void* d_out, int out_size) {
    const float* dc0 = (const float*)d_in[0];
    const float* dc1 = (const float*)d_in[1];
    const float* dc2 = (const float*)d_in[2];
    float* out = (float*)d_out;

    int batch = out_size / ROW_ELEMS;               // 32768 rows
    // 4 warps per row, 16 warps per block -> batch/4 blocks
    int blocks = batch / 4;                         // 8192
    det_prob_kernel<<<blocks, BLOCK>>>(dc0, dc1, dc2, out);
}

// round 11
// speedup vs baseline: 1.3035x; 1.0415x over previous
#include <cuda_runtime.h>
#include <cuda_bf16.h>

// DET_PROB hierarchical cumprod expansion — v6 (FINAL): warp-autonomous,
// no barrier, no smem. Best measured: 82.4us bench / 77.3us ncu,
// 6.43 TB/s = ~93% of the B300 LTS full-chip cap with compulsory-only traffic.
// B0=8, B1=16, B2=16 -> 2048 leaves/row, 128 leaf-groups of 16.
//
// One warp owns 32 contiguous leaf groups (128 chunks, 1/4 of a row).
//  - Each lane front-batches 4 streaming float4 loads (MLP=4, .cs).
//  - Each lane computes ONE prefix (its group) into a register — latency
//    overlapped with the in-flight loads. No smem, no __syncthreads.
//  - Streaming loop fetches the right prefix via __shfl_sync and resolves
//    the within-group-of-16 cumprod with a 4-lane segmented shfl scan.

#define B0 8
#define B1 16
#define B2 16
#define GROUPS 128                 // leaf groups per row
#define ROW_ELEMS 2048
#define BLOCK 256                  // 8 warps
#define WARP_GROUPS 32             // groups per warp
#define WARP_CHUNKS 128            // float4 chunks per warp (4 iters x 32)

__global__ __launch_bounds__(BLOCK) void det_prob_kernel(
    const float* __restrict__ dc0,
    const float* __restrict__ dc1,
    const float* __restrict__ dc2,
    float* __restrict__ out)
{
    int tid  = threadIdx.x;
    int lane = tid & 31;
    size_t gwid = (size_t)blockIdx.x * (BLOCK / 32) + (tid >> 5);

    size_t chunk_base = gwid * WARP_CHUNKS;     // float4 units
    const float4* src = (const float4*)dc2;
    float4*       dst = (float4*)out;

    // ---------- Phase 0: front-batch 4 streaming loads ----------
    float4 x0 = __ldcs(&src[chunk_base + lane + 0 * 32]);
    float4 x1 = __ldcs(&src[chunk_base + lane + 1 * 32]);
    float4 x2 = __ldcs(&src[chunk_base + lane + 2 * 32]);
    float4 x3 = __ldcs(&src[chunk_base + lane + 3 * 32]);

    // ---------- Phase 1: one prefix per lane (overlaps loads) ----------
    // Warp's groups: [gwid*32, gwid*32+32) — always within one row.
    size_t gbase = gwid * WARP_GROUPS;
    size_t row   = gbase >> 7;
    int g  = (int)((gbase + lane) & 127);
    int a0 = g >> 4;
    int a1 = g & 15;

    float pfx;
    {
        // c0 = cumprod(dc0[row])[a0] — broadcast L1 hits
        const float4* r0 = (const float4*)(dc0 + row * B0);
        float4 p0 = __ldg(&r0[0]);
        float4 p1 = __ldg(&r0[1]);
        float v0[8] = {p0.x, p0.y, p0.z, p0.w, p1.x, p1.y, p1.z, p1.w};
        float c0 = v0[0];
#pragma unroll
        for (int k = 1; k < B0; k++)
            c0 *= (k <= a0) ? v0[k] : 1.0f;

        // c1 = within-group cumprod of dc1[row, a0*16 .. +16][a1]
        // Only 2 distinct a0 per warp -> 2 distinct 16B addresses per load.
        const float4* r1 = (const float4*)(dc1 + row * (B0 * B1) + a0 * B1);
        float4 q0 = __ldg(&r1[0]);
        float4 q1 = __ldg(&r1[1]);
        float4 q2 = __ldg(&r1[2]);
        float4 q3 = __ldg(&r1[3]);
        float v1[16] = {q0.x, q0.y, q0.z, q0.w, q1.x, q1.y, q1.z, q1.w,
                        q2.x, q2.y, q2.z, q2.w, q3.x, q3.y, q3.z, q3.w};
        float c1 = v1[0];
#pragma unroll
        for (int k = 1; k < B1; k++)
            c1 *= (k <= a1) ? v1[k] : 1.0f;

        pfx = c0 * c1;
    }

    // ---------- Phase 2: scan + scale + store (no barrier) ----------
    const unsigned mask = 0xFFFFFFFFu;
    int c = lane & 3;                 // chunk-within-group
    int gsel = lane >> 2;             // group slot 0..7 within this iter
    float4 xs[4] = {x0, x1, x2, x3};

#pragma unroll
    for (int it = 0; it < 4; it++) {
        float4 x = xs[it];
        float l0 = x.x;
        float l1 = l0 * x.y;
        float l2 = l1 * x.z;
        float l3 = l2 * x.w;

        // segmented inclusive scan of chunk totals across the 4-lane group
        float s = l3;
        float u = __shfl_up_sync(mask, s, 1);
        if (c >= 1) s *= u;
        u = __shfl_up_sync(mask, s, 2);
        if (c >= 2) s *= u;
        float e = __shfl_up_sync(mask, s, 1);   // exclusive prefix
        if (c == 0) e = 1.0f;

        // fetch this chunk's group prefix from the owning lane
        float pf = __shfl_sync(mask, pfx, it * 8 + gsel);

        float scale = pf * e;
        float4 o;
        o.x = l0 * scale;
        o.y = l1 * scale;
        o.z = l2 * scale;
        o.w = l3 * scale;
        __stcs(&dst[chunk_base + lane + it * 32], o);
    }
}

extern "C" void kernel_launch(void* const* d_in, const int* in_sizes, int n_in,
                              void* d_out, int out_size) {
    const float* dc0 = (const float*)d_in[0];
    const float* dc1 = (const float*)d_in[1];
    const float* dc2 = (const float*)d_in[2];
    float* out = (float*)d_out;

    int batch = out_size / ROW_ELEMS;               // 32768 rows
    // 4 warps per row, 8 warps per block -> batch/2 blocks
    int blocks = batch / 2;                         // 16384
    det_prob_kernel<<<blocks, BLOCK>>>(dc0, dc1, dc2, out);
}